// round 8
// baseline (speedup 1.0000x reference)
#include <cuda_runtime.h>
#include <math_constants.h>

// ROI max pooling, two-phase:
//  1) decode_kernel: 1 thread/ROI packs each of 49 bin windows into an int:
//     base_pixel(8b) | nrows(5b @ bit 8) | ncols(5b @ bit 16).
//  2) pool_kernel: grid (16 slices, 16 imgs, 4 roi-groups), 512 threads.
//     Stages a 32-channel image slice (32KB) + the group's 784 windows into
//     smem, then warp w pools ROI w (lane = channel) over all 49 bins.

#define FM_H 16
#define FM_W 16
#define PH 7
#define PW 7
#define C 512
#define C4 128
#define NROIS 1024
#define NROIS_PER_IMG 64
#define NBINS (PH * PW)
#define SLICE_CH 32
#define SLICE_C4 8
#define NSLICES 16
#define ROIS_PER_BLK 16
#define NPIX (FM_H * FM_W)

__device__ int g_windows[NROIS * NBINS];

__global__ __launch_bounds__(128) void decode_kernel(
    const float4* __restrict__ rois)
{
    const int g = blockIdx.x * 128 + threadIdx.x;
    if (g >= NROIS) return;

    const float4 r = __ldg(&rois[g]);
    // Truncation matches jnp .astype(int32) for positive values.
    const int h0 = (int)((float)FM_H * r.x);
    const int w0 = (int)((float)FM_W * r.y);
    const int h1 = (int)((float)FM_H * r.z);
    const int w1 = (int)((float)FM_W * r.w);
    const int hs = (h1 - h0) / PH;
    const int ws = (w1 - w0) / PW;

    // Reference semantics: bins 0..P-2 span `step` rows, last bin extends to
    // region end. If step<=0, all in-ROI rows fold into the last bin; other
    // bins are empty (nrows=0 -> -inf output).
    int rs[PH], nr[PH], cs[PW], nc[PW];
    #pragma unroll
    for (int bi = 0; bi < PH; ++bi) {
        if (hs > 0) {
            rs[bi] = h0 + bi * hs;
            nr[bi] = (bi == PH - 1) ? (h1 - rs[bi]) : hs;
        } else {
            rs[bi] = (bi == PH - 1) ? h0 : 0;
            nr[bi] = (bi == PH - 1) ? (h1 - h0) : 0;
        }
    }
    #pragma unroll
    for (int bj = 0; bj < PW; ++bj) {
        if (ws > 0) {
            cs[bj] = w0 + bj * ws;
            nc[bj] = (bj == PW - 1) ? (w1 - cs[bj]) : ws;
        } else {
            cs[bj] = (bj == PW - 1) ? w0 : 0;
            nc[bj] = (bj == PW - 1) ? (w1 - w0) : 0;
        }
    }

    int* wout = g_windows + g * NBINS;
    #pragma unroll
    for (int bi = 0; bi < PH; ++bi) {
        #pragma unroll
        for (int bj = 0; bj < PW; ++bj) {
            int base_px = rs[bi] * FM_W + cs[bj];
            wout[bi * PW + bj] = base_px | (nr[bi] << 8) | (nc[bj] << 16);
        }
    }
}

__global__ __launch_bounds__(512) void pool_kernel(
    const float4* __restrict__ fm,    // (16 imgs, 256 px, 128 float4)
    float*        __restrict__ out)   // (1024, 49, 512) float
{
    __shared__ float4 tile4[NPIX * SLICE_C4];       // 32 KB
    __shared__ int    meta[ROIS_PER_BLK * NBINS];   // 784 ints

    const int slice = blockIdx.x;   // 0..15
    const int img   = blockIdx.y;   // 0..15
    const int grp   = blockIdx.z;   // 0..3
    const int tid   = threadIdx.x;  // 0..511
    const int g0    = img * NROIS_PER_IMG + grp * ROIS_PER_BLK;

    // ---- Stage channel slice: 2048 float4, coalesced 128B chunks ----
    {
        const float4* src = fm + (size_t)img * (NPIX * C4) + slice * SLICE_C4;
        #pragma unroll
        for (int i = 0; i < NPIX * SLICE_C4 / 512; ++i) {  // 4 iters
            int idx = i * 512 + tid;
            int px  = idx >> 3;
            int c4  = idx & 7;
            tile4[idx] = __ldg(src + (size_t)px * C4 + c4);
        }
    }
    // ---- Stage this group's windows ----
    for (int idx = tid; idx < ROIS_PER_BLK * NBINS; idx += 512)
        meta[idx] = g_windows[g0 * NBINS + idx];
    __syncthreads();

    const float* tile = (const float*)tile4;   // [256 px][32 ch]
    const int w    = tid >> 5;   // warp = ROI within group (0..15)
    const int lane = tid & 31;   // channel within slice

    const int  g     = g0 + w;
    const int* mrow  = meta + w * NBINS;
    float*     obase = out + (size_t)g * (NBINS * C) + slice * SLICE_CH + lane;

    for (int bin = 0; bin < NBINS; ++bin) {
        const int mw   = mrow[bin];            // uniform -> broadcast
        const int base = mw & 0xFF;
        const float* p = tile + base * SLICE_CH + lane;

        float m;
        if ((mw & 0x001F1F00) == 0x00010100) {
            // 1x1 bin (the common case): plain copy
            m = p[0];
        } else {
            const int nr = (mw >> 8) & 0x1F;
            const int nc = (mw >> 16) & 0x1F;
            m = -CUDART_INF_F;
            for (int r = 0; r < nr; ++r) {
                const float* prow = p + r * (FM_W * SLICE_CH);
                for (int c = 0; c < nc; ++c)
                    m = fmaxf(m, prow[c * SLICE_CH]);
            }
        }
        obase[(size_t)bin * C] = m;
    }
}

extern "C" void kernel_launch(void* const* d_in, const int* in_sizes, int n_in,
                              void* d_out, int out_size) {
    const float4* fm   = (const float4*)d_in[0];
    const float4* rois = (const float4*)d_in[1];
    float*        out  = (float*)d_out;

    decode_kernel<<<(NROIS + 127) / 128, 128>>>(rois);

    dim3 grid(NSLICES, 16, 4);   // slices x images x roi-groups
    pool_kernel<<<grid, 512>>>(fm, out);
}

// round 10
// speedup vs baseline: 2.0947x; 2.0947x over previous
#include <cuda_runtime.h>
#include <math_constants.h>

// ROI max pooling, single kernel, smem-staged, instruction-minimal.
// fm: (16 imgs, 16, 16, 512) f32; rois: (1024,4); out: (1024, 7, 7, 512) f32
//
// Grid (16 slices, 16 imgs, 4 roi-groups) = 1024 blocks x 512 threads.
// Block stages a 32-channel image slice (256 px * 128B = 32KB) into smem.
// Warp = one ROI, lane = one channel of the slice. ROI windows decoded once
// per warp into registers; 49 bins fully unrolled with immediate offsets.

#define FM_H 16
#define FM_W 16
#define PH 7
#define PW 7
#define C 512
#define C4T 128          // 512 ch / 4 in the source layout
#define SLICE_CH 32
#define SLICE_C4 8
#define NPIX 256
#define ROIS_PER_BLK 16

__global__ __launch_bounds__(512, 4) void roipool_kernel(
    const float4* __restrict__ fm,     // (16, 256, 128) float4
    const float4* __restrict__ rois,   // (1024) float4
    float*        __restrict__ out)    // (1024, 49, 512) float
{
    __shared__ float4 tile4[NPIX * SLICE_C4];   // 32 KB
    const int slice = blockIdx.x;   // 0..15
    const int img   = blockIdx.y;   // 0..15
    const int grp   = blockIdx.z;   // 0..3
    const int tid   = threadIdx.x;  // 0..511

    // ---- Stage channel slice: 2048 float4, coalesced ----
    {
        const float4* src = fm + (size_t)img * (NPIX * C4T) + slice * SLICE_C4;
        #pragma unroll
        for (int i = 0; i < 4; ++i) {
            int idx = i * 512 + tid;
            tile4[idx] = __ldg(src + (idx >> 3) * C4T + (idx & 7));
        }
    }
    __syncthreads();

    const float* tile = (const float*)tile4;    // [256 px][32 ch]
    const int w    = tid >> 5;                  // warp = ROI in group
    const int lane = tid & 31;                  // channel in slice
    const int g    = img * 64 + grp * ROIS_PER_BLK + w;

    const float4 r = __ldg(&rois[g]);
    // Truncation matches jnp .astype(int32) for positive values.
    const int h0 = (int)(16.0f * r.x);
    const int w0 = (int)(16.0f * r.y);
    const int h1 = (int)(16.0f * r.z);
    const int w1 = (int)(16.0f * r.w);
    const int hs = (h1 - h0) / PH;
    const int ws = (w1 - w0) / PW;

    // 32-bit element offsets (out has 25.7M floats; fits int)
    float*       obase = out + g * (PH * PW * C) + slice * SLICE_CH + lane;
    const float* tbase = tile + lane;

    if (hs == 1 && ws == 1) {
        // Fast path: bins (bi<6, bj<6) are single pixels; last row/col fat.
        const int nrl = h1 - h0 - (PH - 1);     // >= 1
        const int ncl = w1 - w0 - (PW - 1);     // >= 1
        const float* p00 = tbase + (h0 * FM_W + w0) * SLICE_CH;

        // 36 interior copies: independent LDS+STG pairs, immediate offsets.
        #pragma unroll
        for (int bi = 0; bi < PH - 1; ++bi)
            #pragma unroll
            for (int bj = 0; bj < PW - 1; ++bj)
                obase[(bi * PW + bj) * C] = p00[(bi * FM_W + bj) * SLICE_CH];

        // Right column (bj=6): 1 x ncl windows.
        #pragma unroll
        for (int bi = 0; bi < PH - 1; ++bi) {
            const float* p = p00 + (bi * FM_W + (PW - 1)) * SLICE_CH;
            float m = p[0];
            for (int c = 1; c < ncl; ++c) m = fmaxf(m, p[c * SLICE_CH]);
            obase[(bi * PW + (PW - 1)) * C] = m;
        }
        // Bottom row (bi=6): nrl x 1 windows.
        #pragma unroll
        for (int bj = 0; bj < PW - 1; ++bj) {
            const float* p = p00 + ((PH - 1) * FM_W + bj) * SLICE_CH;
            float m = p[0];
            for (int rr = 1; rr < nrl; ++rr) m = fmaxf(m, p[rr * (FM_W * SLICE_CH)]);
            obase[((PH - 1) * PW + bj) * C] = m;
        }
        // Corner: nrl x ncl.
        {
            const float* p = p00 + ((PH - 1) * FM_W + (PW - 1)) * SLICE_CH;
            float m = -CUDART_INF_F;
            for (int rr = 0; rr < nrl; ++rr)
                for (int c = 0; c < ncl; ++c)
                    m = fmaxf(m, p[(rr * FM_W + c) * SLICE_CH]);
            obase[(PH * PW - 1) * C] = m;
        }
    } else {
        // General path (reference semantics incl. empty bins -> -inf).
        #pragma unroll
        for (int bi = 0; bi < PH; ++bi) {
            int rs_, nr_;
            if (hs > 0) { rs_ = h0 + bi * hs; nr_ = (bi == PH - 1) ? (h1 - rs_) : hs; }
            else        { rs_ = h0;           nr_ = (bi == PH - 1) ? (h1 - h0) : 0; }
            #pragma unroll
            for (int bj = 0; bj < PW; ++bj) {
                int cs_, nc_;
                if (ws > 0) { cs_ = w0 + bj * ws; nc_ = (bj == PW - 1) ? (w1 - cs_) : ws; }
                else        { cs_ = w0;           nc_ = (bj == PW - 1) ? (w1 - w0) : 0; }
                float m = -CUDART_INF_F;
                const float* p = tbase + (rs_ * FM_W + cs_) * SLICE_CH;
                for (int rr = 0; rr < nr_; ++rr)
                    for (int c = 0; c < nc_; ++c)
                        m = fmaxf(m, p[(rr * FM_W + c) * SLICE_CH]);
                obase[(bi * PW + bj) * C] = m;
            }
        }
    }
}

extern "C" void kernel_launch(void* const* d_in, const int* in_sizes, int n_in,
                              void* d_out, int out_size) {
    const float4* fm   = (const float4*)d_in[0];
    const float4* rois = (const float4*)d_in[1];
    float*        out  = (float*)d_out;

    dim3 grid(16, 16, 4);   // slices x images x roi-groups
    roipool_kernel<<<grid, 512>>>(fm, rois, out);
}